// round 14
// baseline (speedup 1.0000x reference)
#include <cuda_runtime.h>
#include <cuda_fp16.h>
#include <stdint.h>

#define VOCAB  50257
#define NSTRIP 786
#define NMT    16
#define TT     (NMT*NSTRIP)
#define GRID   148
#define NTHR   512
#define MATH   6438912ull            // halves per B mat: 786*8192
#define STG_OFF 163840               // bytes: A 64KB + B 2x48KB
#define STG_STRIDE 66
#define STG_FL (128*STG_STRIDE)      // floats per staging buffer (8448)
#define SMEM_BYTES (STG_OFF + 2*STG_FL*4)   // 231424

__device__ __half g_scr[3ull*MATH];  // br, bi, W (fragment-permuted fp16)

static __device__ __forceinline__ uint32_t smem_u32(const void* p){
    uint32_t a; asm("{ .reg .u64 t; cvta.to.shared.u64 t, %1; cvt.u32.u64 %0, t; }":"=r"(a):"l"(p)); return a;
}
static __device__ __forceinline__ uint32_t h2(float lo, float hi){
    __half2 h = __floats2half2_rn(lo, hi);
    return *(uint32_t*)&h;
}
static __device__ __forceinline__ uint32_t hsub2(uint32_t a, uint32_t b){
    uint32_t r; asm("sub.rn.f16x2 %0,%1,%2;":"=r"(r):"r"(a),"r"(b)); return r;
}
static __device__ __forceinline__ uint32_t hadd2(uint32_t a, uint32_t b){
    uint32_t r; asm("add.rn.f16x2 %0,%1,%2;":"=r"(r):"r"(a),"r"(b)); return r;
}
static __device__ __forceinline__ void mma16(float* d, const uint4& a, uint32_t b0, uint32_t b1){
    asm volatile("mma.sync.aligned.m16n8k16.row.col.f32.f16.f16.f32 "
        "{%0,%1,%2,%3}, {%4,%5,%6,%7}, {%8,%9}, {%0,%1,%2,%3};"
        : "+f"(d[0]),"+f"(d[1]),"+f"(d[2]),"+f"(d[3])
        : "r"(a.x),"r"(a.y),"r"(a.z),"r"(a.w),"r"(b0),"r"(b1));
}
#define CPA(dst,src) asm volatile("cp.async.cg.shared.global [%0], [%1], 16;"::"r"(dst),"l"(src):"memory")
#define CPCOMMIT()   asm volatile("cp.async.commit_group;":::"memory")
#define CPWAIT1()    asm volatile("cp.async.wait_group 1;":::"memory")
#define CPWAIT0()    asm volatile("cp.async.wait_group 0;":::"memory")

// ---- prep: fp16 fragment-chunk scratch for br, bi, W ----
__global__ void __launch_bounds__(256) prep_kernel(
    const float* __restrict__ br, const float* __restrict__ bi, const float* __restrict__ W)
{
    unsigned i = blockIdx.x*256u + threadIdx.x;
    unsigned ln = i & 31u, pg = (i>>5)&3u, kk = (i>>7)&7u, q = i>>10;
    unsigned mat = q / 786u, s = q - mat*786u;
    const float* src = (mat==0) ? br : ((mat==1) ? bi : W);
    int lq = ln>>2, lr = ln&3, k0 = kk*16 + lr*2;
    int r0 = s*64 + pg*16 + lq;     if (r0 > VOCAB-1) r0 = VOCAB-1;
    int r1 = s*64 + pg*16 + 8 + lq; if (r1 > VOCAB-1) r1 = VOCAB-1;
    float2 a0 = *(const float2*)(src + (size_t)r0*128 + k0);
    float2 a1 = *(const float2*)(src + (size_t)r0*128 + k0 + 8);
    float2 a2 = *(const float2*)(src + (size_t)r1*128 + k0);
    float2 a3 = *(const float2*)(src + (size_t)r1*128 + k0 + 8);
    uint4 u;
    u.x = h2(a0.x, a0.y);
    u.y = h2(a1.x, a1.y);
    u.z = h2(a2.x, a2.y);
    u.w = h2(a3.x, a3.y);
    *(uint4*)&g_scr[(size_t)mat*MATH + (size_t)s*8192 + (size_t)((kk*4+pg)*32+ln)*8] = u;
}

__global__ void __launch_bounds__(NTHR,1) idec_main(
    const float* __restrict__ pr, const float* __restrict__ pi,
    const float* __restrict__ bb, float* __restrict__ out)
{
    extern __shared__ __align__(16) char smraw[];
    __half* smh = (__half*)smraw;
    float*  stg0 = (float*)(smraw + STG_OFF);
    const uint32_t sbase = smem_u32(smraw);
    const int tid = threadIdx.x, lane = tid&31, wid = tid>>5;
    const int wm = wid&3, wn = wid>>2;          // 4(M) x 4(N) warps, tile 32x16
    const int lq = lane>>2, lr = lane&3;
    const int scol = tid & 63, srow0 = tid >> 6; // sweep geometry

    const int t0 = (int)(((long long)blockIdx.x     * TT) / GRID);
    const int t1 = (int)(((long long)(blockIdx.x+1) * TT) / GRID);

    float c1[2][2][4], c2[2][2][4], c3[2][2][4], cL[2][2][4];
    #pragma unroll
    for (int a=0;a<2;a++)
    #pragma unroll
    for (int n=0;n<2;n++)
    #pragma unroll
    for (int j=0;j<4;j++){ c1[a][n][j]=0.f; c2[a][n][j]=0.f; c3[a][n][j]=0.f; cL[a][n][j]=0.f; }

    auto issueB = [&](int ss, int st){
        #pragma unroll
        for (int ii=0; ii<6; ii++){
            int i = tid + ii*NTHR;
            int ln = i&31, kk=(i>>5)&7, pg=(i>>8)&3, mb=i>>10;
            const __half* src = &g_scr[(size_t)mb*MATH + (size_t)ss*8192
                                       + (size_t)((kk*4+pg)*32+ln)*8];
            uint32_t dst = sbase + (uint32_t)(32768 + st*24576 + mb*8192
                         + ((kk*4+pg)*32+ln)*8)*2u;
            CPA(dst, src);
        }
        CPCOMMIT();
    };

    auto loadA = [&](int mtile){
        for (int i = tid; i < 4096; i += NTHR){
            int ln=i&31, kk=(i>>5)&7, g=(i>>8)&7, m=i>>11;
            int lql=ln>>2, lrl=ln&3, k0=kk*16+lrl*2;
            const float* src = m ? pi : pr;
            size_t r0 = ((size_t)mtile*128 + g*16 + lql)*128;
            size_t r1 = r0 + 8*128;
            float2 v0=*(const float2*)(src+r0+k0);
            float2 v1=*(const float2*)(src+r1+k0);
            float2 v2=*(const float2*)(src+r0+k0+8);
            float2 v3=*(const float2*)(src+r1+k0+8);
            uint4 u;
            u.x = h2(v0.x,v0.y); u.y = h2(v1.x,v1.y);
            u.z = h2(v2.x,v2.y); u.w = h2(v3.x,v3.y);
            *(uint4*)&smh[m*16384 + ((g*8+kk)*32+ln)*8] = u;
        }
    };

    // MMA phase with the previous strip's sweep interleaved (2 units / kk)
    auto mma_sweep = [&](int st, bool pending, int ps, size_t pbase, const float* stgbuf){
        const int bbase = 32768 + st*24576;
        const int gcol = ps*64 + scol;
        const bool ok = pending && (gcol < VOCAB);
        const float bv = ok ? __ldg(bb + gcol) : 0.f;
        float* const op = out + (pbase + srow0)*VOCAB + gcol;
        const float* const sp = stgbuf + srow0*STG_STRIDE + scol;

        uint4 fpr[2][2], fpi[2][2];
        {   // prologue: A fragments for kk=0
            const int off0 = ((wm*2+0)*8)*256 + lane*8;
            const int off1 = ((wm*2+1)*8)*256 + lane*8;
            fpr[0][0] = *(const uint4*)&smh[off0];
            fpr[0][1] = *(const uint4*)&smh[off1];
            fpi[0][0] = *(const uint4*)&smh[16384+off0];
            fpi[0][1] = *(const uint4*)&smh[16384+off1];
        }
        #pragma unroll
        for (int kk=0; kk<8; kk++){
            const int c = kk&1, nx = c^1;
            const int boff = bbase + ((kk*4 + wn)*32 + lane)*8;
            uint4 f1 = *(const uint4*)&smh[boff];
            uint4 f2 = *(const uint4*)&smh[boff+8192];
            uint4 fw = *(const uint4*)&smh[boff+16384];
            if (kk < 7){
                const int off0 = ((wm*2+0)*8+(kk+1))*256 + lane*8;
                const int off1 = ((wm*2+1)*8+(kk+1))*256 + lane*8;
                fpr[nx][0] = *(const uint4*)&smh[off0];
                fpr[nx][1] = *(const uint4*)&smh[off1];
                fpi[nx][0] = *(const uint4*)&smh[16384+off0];
                fpi[nx][1] = *(const uint4*)&smh[16384+off1];
            }
            uint4 fpd[2];
            #pragma unroll
            for (int mt=0; mt<2; mt++){
                fpd[mt].x = hsub2(fpr[c][mt].x, fpi[c][mt].x);
                fpd[mt].y = hsub2(fpr[c][mt].y, fpi[c][mt].y);
                fpd[mt].z = hsub2(fpr[c][mt].z, fpi[c][mt].z);
                fpd[mt].w = hsub2(fpr[c][mt].w, fpi[c][mt].w);
            }
            uint4 f3;
            f3.x = hadd2(f1.x, f2.x); f3.y = hadd2(f1.y, f2.y);
            f3.z = hadd2(f1.z, f2.z); f3.w = hadd2(f1.w, f2.w);
            #pragma unroll
            for (int mt=0; mt<2; mt++){
                mma16(c1[mt][0], fpr[c][mt], f1.x, f1.y);
                mma16(c1[mt][1], fpr[c][mt], f1.z, f1.w);
            }
            if (ok){
                const int rA = kk*2*8;
                op[(size_t)rA*VOCAB] = sp[rA*STG_STRIDE] + bv;
            }
            #pragma unroll
            for (int mt=0; mt<2; mt++){
                mma16(c2[mt][0], fpi[c][mt], f2.x, f2.y);
                mma16(c2[mt][1], fpi[c][mt], f2.z, f2.w);
            }
            #pragma unroll
            for (int mt=0; mt<2; mt++){
                mma16(cL[mt][0], fpr[c][mt], fw.x, fw.y);
                mma16(cL[mt][1], fpr[c][mt], fw.z, fw.w);
            }
            if (ok){
                const int rB = (kk*2+1)*8;
                op[(size_t)rB*VOCAB] = sp[rB*STG_STRIDE] + bv;
            }
            #pragma unroll
            for (int mt=0; mt<2; mt++){
                mma16(c3[mt][0], fpd[mt], f3.x, f3.y);
                mma16(c3[mt][1], fpd[mt], f3.z, f3.w);
            }
        }
    };

    auto stage_accs = [&](float* stgbuf){
        const int colb = wn*16 + lr*2;
        #pragma unroll
        for (int n=0; n<2; n++){
            const int col = colb + n*8;
            #pragma unroll
            for (int mt=0; mt<2; mt++){
                const int row = wm*32 + mt*16 + lq;
                float2 v;
                float m1=c1[mt][n][0], m2=c2[mt][n][0], m3=c3[mt][n][0];
                float re = m1+m2, im = m3-m1+m2;
                v.x = fmaf(re,re, fmaf(im,im, cL[mt][n][0]));
                m1=c1[mt][n][1]; m2=c2[mt][n][1]; m3=c3[mt][n][1];
                re = m1+m2; im = m3-m1+m2;
                v.y = fmaf(re,re, fmaf(im,im, cL[mt][n][1]));
                *(float2*)&stgbuf[row*STG_STRIDE + col] = v;
                m1=c1[mt][n][2]; m2=c2[mt][n][2]; m3=c3[mt][n][2];
                re = m1+m2; im = m3-m1+m2;
                v.x = fmaf(re,re, fmaf(im,im, cL[mt][n][2]));
                m1=c1[mt][n][3]; m2=c2[mt][n][3]; m3=c3[mt][n][3];
                re = m1+m2; im = m3-m1+m2;
                v.y = fmaf(re,re, fmaf(im,im, cL[mt][n][3]));
                *(float2*)&stgbuf[(row+8)*STG_STRIDE + col] = v;
            }
        }
        #pragma unroll
        for (int a=0;a<2;a++)
        #pragma unroll
        for (int n=0;n<2;n++)
        #pragma unroll
        for (int j=0;j<4;j++){ c1[a][n][j]=0.f; c2[a][n][j]=0.f; c3[a][n][j]=0.f; cL[a][n][j]=0.f; }
    };

    int cur_mtile = -1;
    bool pending = false;
    int ps = 0; size_t pbase = 0;
    int pstg = 0;   // sweep reads stg0+pstg*STG_FL; stage writes the other

    issueB(t0 % NSTRIP, t0 & 1);

    for (int t = t0; t < t1; t++){
        const int mtile = t / NSTRIP;
        const int s = t - mtile*NSTRIP;
        if (mtile != cur_mtile){
            __syncthreads();          // prior A readers done
            loadA(mtile);
            cur_mtile = mtile;
        }
        __syncthreads();              // orders: stage writes->sweep reads; mma(t-1) B reads->issueB(t+1)
        if (t+1 < t1) issueB((t+1) % NSTRIP, (t+1) & 1);
        else          CPCOMMIT();
        CPWAIT1();                    // B group t complete
        mma_sweep(t & 1, pending, ps, pbase, stg0 + pstg*STG_FL);
        stage_accs(stg0 + (pstg^1)*STG_FL);
        pending = true; ps = s; pbase = (size_t)mtile*128; pstg ^= 1;
    }

    // tail: flush last strip's sweep (buffer pstg holds it after the final flip)
    __syncthreads();
    CPWAIT0();
    if (pending){
        const int gcol = ps*64 + scol;
        if (gcol < VOCAB){
            const float bv = __ldg(bb + gcol);
            float* const op = out + (pbase + srow0)*VOCAB + gcol;
            const float* const sp = stg0 + pstg*STG_FL + srow0*STG_STRIDE + scol;
            #pragma unroll
            for (int it=0; it<16; it++)
                op[(size_t)(it*8)*VOCAB] = sp[it*8*STG_STRIDE] + bv;
        }
    }
}

extern "C" void kernel_launch(void* const* d_in, const int* in_sizes, int n_in,
                              void* d_out, int out_size)
{
    const float* pr = (const float*)d_in[0];
    const float* pi = (const float*)d_in[1];
    const float* br = (const float*)d_in[2];
    const float* bi = (const float*)d_in[3];
    const float* W  = (const float*)d_in[4];
    const float* bb = (const float*)d_in[5];

    prep_kernel<<<9432, 256>>>(br, bi, W);
    cudaFuncSetAttribute(idec_main, cudaFuncAttributeMaxDynamicSharedMemorySize, SMEM_BYTES);
    idec_main<<<GRID, NTHR, SMEM_BYTES>>>(pr, pi, bb, (float*)d_out);
}

// round 15
// speedup vs baseline: 1.1032x; 1.1032x over previous
#include <cuda_runtime.h>
#include <cuda_fp16.h>
#include <stdint.h>

#define VOCAB  50257
#define NSTRIP 786
#define NMT    16
#define TT     (NMT*NSTRIP)
#define GRID   148
#define NTHR   512
#define MATH   6438912ull            // halves per B mat: 786*8192
#define STG_OFF 163840               // bytes: A 64KB + B 2x48KB
#define STG_FL  8192                 // floats per staging buffer (128*64, swizzled)
#define SMEM_BYTES (STG_OFF + 2*STG_FL*4)   // 229376

__device__ __half g_scr[3ull*MATH];  // br, bi, W (fragment-permuted fp16)

static __device__ __forceinline__ uint32_t smem_u32(const void* p){
    uint32_t a; asm("{ .reg .u64 t; cvta.to.shared.u64 t, %1; cvt.u32.u64 %0, t; }":"=r"(a):"l"(p)); return a;
}
static __device__ __forceinline__ uint32_t h2(float lo, float hi){
    __half2 h = __floats2half2_rn(lo, hi);
    return *(uint32_t*)&h;
}
static __device__ __forceinline__ uint32_t hsub2(uint32_t a, uint32_t b){
    uint32_t r; asm("sub.rn.f16x2 %0,%1,%2;":"=r"(r):"r"(a),"r"(b)); return r;
}
static __device__ __forceinline__ uint32_t hadd2(uint32_t a, uint32_t b){
    uint32_t r; asm("add.rn.f16x2 %0,%1,%2;":"=r"(r):"r"(a),"r"(b)); return r;
}
static __device__ __forceinline__ void mma16(float* d, const uint4& a, uint32_t b0, uint32_t b1){
    asm volatile("mma.sync.aligned.m16n8k16.row.col.f32.f16.f16.f32 "
        "{%0,%1,%2,%3}, {%4,%5,%6,%7}, {%8,%9}, {%0,%1,%2,%3};"
        : "+f"(d[0]),"+f"(d[1]),"+f"(d[2]),"+f"(d[3])
        : "r"(a.x),"r"(a.y),"r"(a.z),"r"(a.w),"r"(b0),"r"(b1));
}
#define CPA(dst,src) asm volatile("cp.async.cg.shared.global [%0], [%1], 16;"::"r"(dst),"l"(src):"memory")
#define CPCOMMIT()   asm volatile("cp.async.commit_group;":::"memory")
#define CPWAIT1()    asm volatile("cp.async.wait_group 1;":::"memory")
#define CPWAIT0()    asm volatile("cp.async.wait_group 0;":::"memory")

// ---- prep: fp16 fragment-chunk scratch for br, bi, W ----
__global__ void __launch_bounds__(256) prep_kernel(
    const float* __restrict__ br, const float* __restrict__ bi, const float* __restrict__ W)
{
    unsigned i = blockIdx.x*256u + threadIdx.x;
    unsigned ln = i & 31u, pg = (i>>5)&3u, kk = (i>>7)&7u, q = i>>10;
    unsigned mat = q / 786u, s = q - mat*786u;
    const float* src = (mat==0) ? br : ((mat==1) ? bi : W);
    int lq = ln>>2, lr = ln&3, k0 = kk*16 + lr*2;
    int r0 = s*64 + pg*16 + lq;     if (r0 > VOCAB-1) r0 = VOCAB-1;
    int r1 = s*64 + pg*16 + 8 + lq; if (r1 > VOCAB-1) r1 = VOCAB-1;
    float2 a0 = *(const float2*)(src + (size_t)r0*128 + k0);
    float2 a1 = *(const float2*)(src + (size_t)r0*128 + k0 + 8);
    float2 a2 = *(const float2*)(src + (size_t)r1*128 + k0);
    float2 a3 = *(const float2*)(src + (size_t)r1*128 + k0 + 8);
    uint4 u;
    u.x = h2(a0.x, a0.y);
    u.y = h2(a1.x, a1.y);
    u.z = h2(a2.x, a2.y);
    u.w = h2(a3.x, a3.y);
    *(uint4*)&g_scr[(size_t)mat*MATH + (size_t)s*8192 + (size_t)((kk*4+pg)*32+ln)*8] = u;
}

__global__ void __launch_bounds__(NTHR,1) idec_main(
    const float* __restrict__ pr, const float* __restrict__ pi,
    const float* __restrict__ bb, float* __restrict__ out)
{
    extern __shared__ __align__(16) char smraw[];
    __half* smh = (__half*)smraw;
    float*  stg0 = (float*)(smraw + STG_OFF);
    const uint32_t sbase = smem_u32(smraw);
    const int tid = threadIdx.x, lane = tid&31, wid = tid>>5;
    const int wm = wid&3, wn = wid>>2;          // 4(M) x 4(N) warps, tile 32x16
    const int lq = lane>>2, lr = lane&3;
    const int scol = tid & 63, srow0 = tid >> 6; // sweep geometry

    const int t0 = (int)(((long long)blockIdx.x     * TT) / GRID);
    const int t1 = (int)(((long long)(blockIdx.x+1) * TT) / GRID);

    float c1[2][2][4], c2[2][2][4], c3[2][2][4], cL[2][2][4];
    #pragma unroll
    for (int a=0;a<2;a++)
    #pragma unroll
    for (int n=0;n<2;n++)
    #pragma unroll
    for (int j=0;j<4;j++){ c1[a][n][j]=0.f; c2[a][n][j]=0.f; c3[a][n][j]=0.f; cL[a][n][j]=0.f; }

    auto issueB = [&](int ss, int st){
        #pragma unroll
        for (int ii=0; ii<6; ii++){
            int i = tid + ii*NTHR;
            int ln = i&31, kk=(i>>5)&7, pg=(i>>8)&3, mb=i>>10;
            const __half* src = &g_scr[(size_t)mb*MATH + (size_t)ss*8192
                                       + (size_t)((kk*4+pg)*32+ln)*8];
            uint32_t dst = sbase + (uint32_t)(32768 + st*24576 + mb*8192
                         + ((kk*4+pg)*32+ln)*8)*2u;
            CPA(dst, src);
        }
        CPCOMMIT();
    };

    auto loadA = [&](int mtile){
        for (int i = tid; i < 4096; i += NTHR){
            int ln=i&31, kk=(i>>5)&7, g=(i>>8)&7, m=i>>11;
            int lql=ln>>2, lrl=ln&3, k0=kk*16+lrl*2;
            const float* src = m ? pi : pr;
            size_t r0 = ((size_t)mtile*128 + g*16 + lql)*128;
            size_t r1 = r0 + 8*128;
            float2 v0=*(const float2*)(src+r0+k0);
            float2 v1=*(const float2*)(src+r1+k0);
            float2 v2=*(const float2*)(src+r0+k0+8);
            float2 v3=*(const float2*)(src+r1+k0+8);
            uint4 u;
            u.x = h2(v0.x,v0.y); u.y = h2(v1.x,v1.y);
            u.z = h2(v2.x,v2.y); u.w = h2(v3.x,v3.y);
            *(uint4*)&smh[m*16384 + ((g*8+kk)*32+ln)*8] = u;
        }
    };

    // MMA phase with the previous strip's sweep interleaved (2 units / kk)
    auto mma_sweep = [&](int st, bool pending, int ps, size_t pbase, const float* stgbuf){
        const int bbase = 32768 + st*24576;
        const int gcol = ps*64 + scol;
        const bool ok = pending && (gcol < VOCAB);
        const float bv = ok ? __ldg(bb + gcol) : 0.f;
        float* const op = out + (pbase + srow0)*VOCAB + gcol;
        // swizzled staging read base: row&3 invariant across it*8 steps
        const int scol2 = (scol ^ ((srow0 & 3) << 3)) & 63;
        const float* const sp = stgbuf + srow0*64 + scol2;

        uint4 fpr[2][2], fpi[2][2];
        {   // prologue: A fragments for kk=0
            const int off0 = ((wm*2+0)*8)*256 + lane*8;
            const int off1 = ((wm*2+1)*8)*256 + lane*8;
            fpr[0][0] = *(const uint4*)&smh[off0];
            fpr[0][1] = *(const uint4*)&smh[off1];
            fpi[0][0] = *(const uint4*)&smh[16384+off0];
            fpi[0][1] = *(const uint4*)&smh[16384+off1];
        }
        #pragma unroll
        for (int kk=0; kk<8; kk++){
            const int c = kk&1, nx = c^1;
            const int boff = bbase + ((kk*4 + wn)*32 + lane)*8;
            uint4 f1 = *(const uint4*)&smh[boff];
            uint4 f2 = *(const uint4*)&smh[boff+8192];
            uint4 fw = *(const uint4*)&smh[boff+16384];
            if (kk < 7){
                const int off0 = ((wm*2+0)*8+(kk+1))*256 + lane*8;
                const int off1 = ((wm*2+1)*8+(kk+1))*256 + lane*8;
                fpr[nx][0] = *(const uint4*)&smh[off0];
                fpr[nx][1] = *(const uint4*)&smh[off1];
                fpi[nx][0] = *(const uint4*)&smh[16384+off0];
                fpi[nx][1] = *(const uint4*)&smh[16384+off1];
            }
            uint4 fpd[2];
            #pragma unroll
            for (int mt=0; mt<2; mt++){
                fpd[mt].x = hsub2(fpr[c][mt].x, fpi[c][mt].x);
                fpd[mt].y = hsub2(fpr[c][mt].y, fpi[c][mt].y);
                fpd[mt].z = hsub2(fpr[c][mt].z, fpi[c][mt].z);
                fpd[mt].w = hsub2(fpr[c][mt].w, fpi[c][mt].w);
            }
            uint4 f3;
            f3.x = hadd2(f1.x, f2.x); f3.y = hadd2(f1.y, f2.y);
            f3.z = hadd2(f1.z, f2.z); f3.w = hadd2(f1.w, f2.w);
            #pragma unroll
            for (int mt=0; mt<2; mt++){
                mma16(c1[mt][0], fpr[c][mt], f1.x, f1.y);
                mma16(c1[mt][1], fpr[c][mt], f1.z, f1.w);
            }
            if (ok){
                const int rA = kk*2*8;
                op[(size_t)rA*VOCAB] = sp[rA*64] + bv;
            }
            #pragma unroll
            for (int mt=0; mt<2; mt++){
                mma16(c2[mt][0], fpi[c][mt], f2.x, f2.y);
                mma16(c2[mt][1], fpi[c][mt], f2.z, f2.w);
            }
            #pragma unroll
            for (int mt=0; mt<2; mt++){
                mma16(cL[mt][0], fpr[c][mt], fw.x, fw.y);
                mma16(cL[mt][1], fpr[c][mt], fw.z, fw.w);
            }
            if (ok){
                const int rB = (kk*2+1)*8;
                op[(size_t)rB*VOCAB] = sp[rB*64] + bv;
            }
            #pragma unroll
            for (int mt=0; mt<2; mt++){
                mma16(c3[mt][0], fpd[mt], f3.x, f3.y);
                mma16(c3[mt][1], fpd[mt], f3.z, f3.w);
            }
        }
    };

    auto stage_accs = [&](float* stgbuf){
        const int colb = wn*16 + lr*2;
        const int swz = (lq & 3) << 3;          // row&3 == lq&3, invariant for row and row+8
        #pragma unroll
        for (int n=0; n<2; n++){
            const int col = (colb + n*8) ^ swz; // bits 0-2 of col untouched (swz >= bit3)
            #pragma unroll
            for (int mt=0; mt<2; mt++){
                const int row = wm*32 + mt*16 + lq;
                float2 v;
                float m1=c1[mt][n][0], m2=c2[mt][n][0], m3=c3[mt][n][0];
                float re = m1+m2, im = m3-m1+m2;
                v.x = fmaf(re,re, fmaf(im,im, cL[mt][n][0]));
                m1=c1[mt][n][1]; m2=c2[mt][n][1]; m3=c3[mt][n][1];
                re = m1+m2; im = m3-m1+m2;
                v.y = fmaf(re,re, fmaf(im,im, cL[mt][n][1]));
                *(float2*)&stgbuf[row*64 + col] = v;
                m1=c1[mt][n][2]; m2=c2[mt][n][2]; m3=c3[mt][n][2];
                re = m1+m2; im = m3-m1+m2;
                v.x = fmaf(re,re, fmaf(im,im, cL[mt][n][2]));
                m1=c1[mt][n][3]; m2=c2[mt][n][3]; m3=c3[mt][n][3];
                re = m1+m2; im = m3-m1+m2;
                v.y = fmaf(re,re, fmaf(im,im, cL[mt][n][3]));
                *(float2*)&stgbuf[(row+8)*64 + col] = v;
            }
        }
        #pragma unroll
        for (int a=0;a<2;a++)
        #pragma unroll
        for (int n=0;n<2;n++)
        #pragma unroll
        for (int j=0;j<4;j++){ c1[a][n][j]=0.f; c2[a][n][j]=0.f; c3[a][n][j]=0.f; cL[a][n][j]=0.f; }
    };

    int cur_mtile = -1;
    bool pending = false;
    int ps = 0; size_t pbase = 0;
    int pstg = 0;   // sweep reads stg0+pstg*STG_FL; stage writes the other

    issueB(t0 % NSTRIP, t0 & 1);

    for (int t = t0; t < t1; t++){
        const int mtile = t / NSTRIP;
        const int s = t - mtile*NSTRIP;
        if (mtile != cur_mtile){
            __syncthreads();          // prior A readers done
            loadA(mtile);
            cur_mtile = mtile;
        }
        __syncthreads();              // orders: stage writes->sweep reads; mma(t-1) B reads->issueB(t+1)
        if (t+1 < t1) issueB((t+1) % NSTRIP, (t+1) & 1);
        else          CPCOMMIT();
        CPWAIT1();                    // B group t complete
        mma_sweep(t & 1, pending, ps, pbase, stg0 + pstg*STG_FL);
        stage_accs(stg0 + (pstg^1)*STG_FL);
        pending = true; ps = s; pbase = (size_t)mtile*128; pstg ^= 1;
    }

    // tail: flush last strip's sweep (buffer pstg holds it after the final flip)
    __syncthreads();
    CPWAIT0();
    if (pending){
        const int gcol = ps*64 + scol;
        if (gcol < VOCAB){
            const float bv = __ldg(bb + gcol);
            float* const op = out + (pbase + srow0)*VOCAB + gcol;
            const int scol2 = (scol ^ ((srow0 & 3) << 3)) & 63;
            const float* const sp = stg0 + pstg*STG_FL + srow0*64 + scol2;
            #pragma unroll
            for (int it=0; it<16; it++)
                op[(size_t)(it*8)*VOCAB] = sp[it*8*64] + bv;
        }
    }
}

extern "C" void kernel_launch(void* const* d_in, const int* in_sizes, int n_in,
                              void* d_out, int out_size)
{
    const float* pr = (const float*)d_in[0];
    const float* pi = (const float*)d_in[1];
    const float* br = (const float*)d_in[2];
    const float* bi = (const float*)d_in[3];
    const float* W  = (const float*)d_in[4];
    const float* bb = (const float*)d_in[5];

    prep_kernel<<<9432, 256>>>(br, bi, W);
    cudaFuncSetAttribute(idec_main, cudaFuncAttributeMaxDynamicSharedMemorySize, SMEM_BYTES);
    idec_main<<<GRID, NTHR, SMEM_BYTES>>>(pr, pi, bb, (float*)d_out);
}